// round 16
// baseline (speedup 1.0000x reference)
#include <cuda_runtime.h>
#include <cuda_bf16.h>
#include <cstdint>

#define N_NODES 8192
#define FIN 128
#define FOUT 64
#define EMAX 262144
#define SA 72            // staging row stride in bf16 elems (144 B): ldmatrix conflict-free

// Scratch (allocation-free rule: __device__ globals)
__device__ int   g_cnt[N_NODES];          // zero at entry; gemm dead-blocks re-zero it
__device__ float g_dinv[N_NODES];
__device__ float g_h[N_NODES * FOUT];
__device__ float g_z[N_NODES * FOUT];

// ---------------------------------------------------------------- launch 1: fused edge-count + h GEMM
__global__ void __launch_bounds__(256) k_count_h(const int* __restrict__ ei, int E,
                                                 const float* __restrict__ x,
                                                 const float* __restrict__ W) {
    int tid = threadIdx.x;
    if (blockIdx.x < 1024) {
        int e = blockIdx.x * 256 + tid;
        if (e < E) atomicAdd(&g_cnt[ei[E + e]], 1);
        return;
    }
    __shared__ float sW[FIN * FOUT];   // 32 KB
#pragma unroll
    for (int i = 0; i < 8; i++)
        ((float4*)sW)[tid + i * 256] = ((const float4*)W)[tid + i * 256];
    __syncthreads();

    const int hb = blockIdx.x - 1024;            // 0..255
    const int n = hb * 32 + (tid & 31);          // node (lanes consecutive -> coalesced x)
    const int g = tid >> 5;                      // out group 0..7 (warp-uniform -> LDS bcast)
    const float4* sW4 = (const float4*)sW;

    unsigned long long acc2[4];
#pragma unroll
    for (int i = 0; i < 4; i++) acc2[i] = 0ull;

#pragma unroll 8
    for (int k = 0; k < FIN; k++) {
        float xv = __ldg(&x[k * N_NODES + n]);   // 128B coalesced per warp
        unsigned long long a2;
        asm("mov.b64 %0, {%1, %1};" : "=l"(a2) : "f"(xv));
        float4 w0 = sW4[k * 16 + g * 2];         // broadcast LDS.128
        float4 w1 = sW4[k * 16 + g * 2 + 1];
        unsigned long long p0, p1, p2, p3;
        asm("mov.b64 %0, {%1, %2};" : "=l"(p0) : "f"(w0.x), "f"(w0.y));
        asm("mov.b64 %0, {%1, %2};" : "=l"(p1) : "f"(w0.z), "f"(w0.w));
        asm("mov.b64 %0, {%1, %2};" : "=l"(p2) : "f"(w1.x), "f"(w1.y));
        asm("mov.b64 %0, {%1, %2};" : "=l"(p3) : "f"(w1.z), "f"(w1.w));
        asm("fma.rn.f32x2 %0, %1, %2, %0;" : "+l"(acc2[0]) : "l"(a2), "l"(p0));
        asm("fma.rn.f32x2 %0, %1, %2, %0;" : "+l"(acc2[1]) : "l"(a2), "l"(p1));
        asm("fma.rn.f32x2 %0, %1, %2, %0;" : "+l"(acc2[2]) : "l"(a2), "l"(p2));
        asm("fma.rn.f32x2 %0, %1, %2, %0;" : "+l"(acc2[3]) : "l"(a2), "l"(p3));
    }
    float* hp = &g_h[n * FOUT + g * 8];
    float v0, v1, v2, v3, v4, v5, v6, v7;
    asm("mov.b64 {%0, %1}, %2;" : "=f"(v0), "=f"(v1) : "l"(acc2[0]));
    asm("mov.b64 {%0, %1}, %2;" : "=f"(v2), "=f"(v3) : "l"(acc2[1]));
    asm("mov.b64 {%0, %1}, %2;" : "=f"(v4), "=f"(v5) : "l"(acc2[2]));
    asm("mov.b64 {%0, %1}, %2;" : "=f"(v6), "=f"(v7) : "l"(acc2[3]));
    ((float4*)hp)[0] = make_float4(v0, v1, v2, v3);
    ((float4*)hp)[1] = make_float4(v4, v5, v6, v7);
}

// ---------------------------------------------------------------- launch 2: dinv + z = h*dinv^2 + b
__global__ void k_zinit(const float* __restrict__ b) {
    int gid = blockIdx.x * blockDim.x + threadIdx.x;   // N * 16
    int n = gid >> 4, q = gid & 15;
    float dinv = rsqrtf((float)(g_cnt[n] + 1));
    if (q == 0) g_dinv[n] = dinv;
    float c = dinv * dinv;
    float4 h = *(const float4*)&g_h[n * FOUT + q * 4];
    float4 bb = __ldg(&((const float4*)b)[q]);
    float4 z;
    z.x = fmaf(h.x, c, bb.x);
    z.y = fmaf(h.y, c, bb.y);
    z.z = fmaf(h.z, c, bb.z);
    z.w = fmaf(h.w, c, bb.w);
    *(float4*)&g_z[n * FOUT + q * 4] = z;
}

// ---------------------------------------------------------------- launch 3: edge scatter, vector red
__global__ void k_edges(const int* __restrict__ ei, int E) {
    int gid = blockIdx.x * blockDim.x + threadIdx.x;   // E * 16
    int e = gid >> 4, q = gid & 15;
    if (e >= E) return;
    int s = __ldg(&ei[e]);
    int d = __ldg(&ei[E + e]);
    float c = __ldg(&g_dinv[s]) * __ldg(&g_dinv[d]);
    float4 h = *(const float4*)&g_h[s * FOUT + q * 4];
    float* zp = &g_z[d * FOUT + q * 4];
    asm volatile("red.global.add.v4.f32 [%0], {%1, %2, %3, %4};"
                 :: "l"(zp), "f"(h.x * c), "f"(h.y * c), "f"(h.z * c), "f"(h.w * c)
                 : "memory");
}

// ---------------------------------------------------------------- launch 4: split-bf16 HMMA, 128x64 tiles
__device__ __forceinline__ uint32_t smem_u32(const void* p) {
    uint32_t a;
    asm("{ .reg .u64 t; cvta.to.shared.u64 t, %1; cvt.u32.u64 %0, t; }" : "=r"(a) : "l"(p));
    return a;
}
__device__ __forceinline__ float sigmoid_tanh(float v) {
    float t;
    asm("tanh.approx.f32 %0, %1;" : "=f"(t) : "f"(0.5f * v));
    return fmaf(0.5f, t, 0.5f);
}
__device__ __forceinline__ void split2(float x, float y, uint32_t& hi, uint32_t& lo) {
    asm("cvt.rn.bf16x2.f32 %0, %1, %2;" : "=r"(hi) : "f"(y), "f"(x));   // hi16=y, lo16=x
    float hx = __uint_as_float(hi << 16);
    float hy = __uint_as_float(hi & 0xFFFF0000u);
    float rx = x - hx, ry = y - hy;
    asm("cvt.rn.bf16x2.f32 %0, %1, %2;" : "=r"(lo) : "f"(ry), "f"(rx));
}
#define LDSM4(r0, r1, r2, r3, addr) \
    asm volatile("ldmatrix.sync.aligned.m8n8.x4.shared.b16 {%0,%1,%2,%3}, [%4];" \
                 : "=r"(r0), "=r"(r1), "=r"(r2), "=r"(r3) : "r"(addr))
#define MMA16816(d, a, b0v, b1v) \
    asm volatile("mma.sync.aligned.m16n8k16.row.col.f32.bf16.bf16.f32 " \
                 "{%0,%1,%2,%3}, {%4,%5,%6,%7}, {%8,%9}, {%0,%1,%2,%3};" \
                 : "+f"((d)[0]), "+f"((d)[1]), "+f"((d)[2]), "+f"((d)[3]) \
                 : "r"((a)[0]), "r"((a)[1]), "r"((a)[2]), "r"((a)[3]), \
                   "r"(b0v), "r"(b1v))

#define A_BYTES (128 * SA * 2)      // 18432
#define B_BYTES (64 * SA * 2)       //  9216
#define GEMM_SMEM (2 * A_BYTES + 2 * B_BYTES)   // 55296 -> 3 CTAs/SM

__global__ void __launch_bounds__(256, 3) k_gemm_mma(float* __restrict__ out) {
    const int bi = blockIdx.y, bj = blockIdx.x;     // bi: 128-row tile, bj: 64-col tile
    const int tid = threadIdx.x, lane = tid & 31, wid = tid >> 5;
    if (bj < 2 * bi) {
        if (bj == 0 && bi >= 1 && bi <= 32)
            g_cnt[(bi - 1) * 256 + tid] = 0;        // re-zero for next replay (dead blocks)
        return;
    }
    const int i0 = bi * 128, j0 = bj * 64;

    extern __shared__ char dsm[];
    char* pAH = dsm;
    char* pAL = pAH + A_BYTES;
    char* pBH = pAL + A_BYTES;
    char* pBL = pBH + B_BYTES;

    // ---- stage + bf16 split: A 128 rows, B 64 rows ----
#pragma unroll
    for (int it = 0; it < 8; it++) {
        int idx = tid + it * 256;          // 0..2047
        int row = idx >> 4, q = idx & 15;
        uint32_t o = (uint32_t)(row * (SA * 2) + q * 8);
        float4 v = *(const float4*)&g_z[(i0 + row) * FOUT + q * 4];
        uint32_t h0, l0, h1, l1;
        split2(v.x, v.y, h0, l0);
        split2(v.z, v.w, h1, l1);
        *(uint2*)(pAH + o) = make_uint2(h0, h1);
        *(uint2*)(pAL + o) = make_uint2(l0, l1);
    }
#pragma unroll
    for (int it = 0; it < 4; it++) {
        int idx = tid + it * 256;          // 0..1023
        int row = idx >> 4, q = idx & 15;
        uint32_t o = (uint32_t)(row * (SA * 2) + q * 8);
        float4 u = *(const float4*)&g_z[(j0 + row) * FOUT + q * 4];
        uint32_t h0, l0, h1, l1;
        split2(u.x, u.y, h0, l0);
        split2(u.z, u.w, h1, l1);
        *(uint2*)(pBH + o) = make_uint2(h0, h1);
        *(uint2*)(pBL + o) = make_uint2(l0, l1);
    }
    __syncthreads();

    const uint32_t aAH = smem_u32(pAH), aAL = smem_u32(pAL);
    const uint32_t aBH = smem_u32(pBH), aBL = smem_u32(pBL);

    const int wr = wid & 3, wc = wid >> 2;          // 4 x 2 warps
    const int mbase = wr * 32, nbase = wc * 32;     // warp: 32 rows x 32 cols

    float d[2][4][4];
#pragma unroll
    for (int mi = 0; mi < 2; mi++)
#pragma unroll
        for (int j = 0; j < 4; j++)
#pragma unroll
            for (int t = 0; t < 4; t++) d[mi][j][t] = 0.f;

    const int arow = lane & 15, ahalf = lane >> 4;
    const int brow = (lane & 7) + 8 * ((lane >> 3) & 1);
    const int bhalf = lane >> 4;

#pragma unroll
    for (int ks = 0; ks < 4; ks++) {
        const int kb = ks * 16;
        uint32_t ah[2][4], al[2][4];
#pragma unroll
        for (int mi = 0; mi < 2; mi++) {
            uint32_t off = (uint32_t)(((mbase + mi * 16 + arow) * SA + kb + ahalf * 8) * 2);
            LDSM4(ah[mi][0], ah[mi][1], ah[mi][2], ah[mi][3], aAH + off);
            LDSM4(al[mi][0], al[mi][1], al[mi][2], al[mi][3], aAL + off);
        }
        uint32_t bh[4][2], bl[4][2];
#pragma unroll
        for (int jh = 0; jh < 2; jh++) {
            uint32_t off = (uint32_t)(((nbase + jh * 16 + brow) * SA + kb + bhalf * 8) * 2);
            uint32_t r0, r1, r2, r3;
            LDSM4(r0, r1, r2, r3, aBH + off);
            bh[jh * 2][0] = r0; bh[jh * 2][1] = r2;
            bh[jh * 2 + 1][0] = r1; bh[jh * 2 + 1][1] = r3;
            LDSM4(r0, r1, r2, r3, aBL + off);
            bl[jh * 2][0] = r0; bl[jh * 2][1] = r2;
            bl[jh * 2 + 1][0] = r1; bl[jh * 2 + 1][1] = r3;
        }
#pragma unroll
        for (int mi = 0; mi < 2; mi++)
#pragma unroll
            for (int j = 0; j < 4; j++) {
                MMA16816(d[mi][j], ah[mi], bh[j][0], bh[j][1]);
                MMA16816(d[mi][j], ah[mi], bl[j][0], bl[j][1]);
                MMA16816(d[mi][j], al[mi], bh[j][0], bh[j][1]);
            }
    }

    // ---- epilogue: sigmoid + direct & mirrored stores ----
    const int fr = lane >> 2;            // 0..7
    const int cc = (lane & 3) * 2;
#pragma unroll
    for (int mi = 0; mi < 2; mi++) {
        const int gr0 = i0 + mbase + mi * 16 + fr;
#pragma unroll
        for (int j = 0; j < 4; j++) {
            const int gc = j0 + nbase + j * 8 + cc;
            float f0 = sigmoid_tanh(d[mi][j][0]);
            float f1 = sigmoid_tanh(d[mi][j][1]);
            float f2 = sigmoid_tanh(d[mi][j][2]);
            float f3 = sigmoid_tanh(d[mi][j][3]);
            *(float2*)&out[(size_t)gr0 * N_NODES + gc] = make_float2(f0, f1);
            *(float2*)&out[(size_t)(gr0 + 8) * N_NODES + gc] = make_float2(f2, f3);
            // mirror (overlap with direct on straddling tiles writes identical values)
            out[(size_t)gc * N_NODES + gr0]           = f0;
            out[(size_t)(gc + 1) * N_NODES + gr0]     = f1;
            out[(size_t)gc * N_NODES + gr0 + 8]       = f2;
            out[(size_t)(gc + 1) * N_NODES + gr0 + 8] = f3;
        }
    }
}

// ----------------------------------------------------------------
extern "C" void kernel_launch(void* const* d_in, const int* in_sizes, int n_in,
                              void* d_out, int out_size) {
    const float* x  = (const float*)d_in[0];       // [128, 8192]
    const int*   ei = (const int*)d_in[1];         // [2, E] int32
    const float* W  = (const float*)d_in[2];       // [128, 64]
    const float* b  = (const float*)d_in[3];       // [64]
    float* out = (float*)d_out;                    // [8192, 8192]
    const int E = in_sizes[1] / 2;

    cudaFuncSetAttribute(k_gemm_mma, cudaFuncAttributeMaxDynamicSharedMemorySize, GEMM_SMEM);

    k_count_h<<<1024 + 256, 256>>>(ei, E, x, W);             // 1
    k_zinit<<<(N_NODES * 16) / 256, 256>>>(b);               // 2
    k_edges<<<(E * 16) / 256, 256>>>(ei, E);                 // 3
    dim3 grid(N_NODES / 64, N_NODES / 128);                  // 128 x 64 (bj x bi)
    k_gemm_mma<<<grid, 256, GEMM_SMEM>>>(out);               // 4 <- ncu captures this
}

// round 17
// speedup vs baseline: 1.5609x; 1.5609x over previous
#include <cuda_runtime.h>
#include <cuda_bf16.h>
#include <cstdint>

#define N_NODES 8192
#define FIN 128
#define FOUT 64
#define EMAX 262144
#define SA 72            // staging row stride in bf16 elems (144 B): ldmatrix conflict-free

// Scratch (allocation-free rule: __device__ globals)
__device__ int   g_cnt[N_NODES];          // zero at entry; gemm dead-blocks re-zero it
__device__ float g_dinv[N_NODES];
__device__ float g_h[N_NODES * FOUT];
__device__ float g_z[N_NODES * FOUT];

// ---------------------------------------------------------------- launch 1: fused edge-count + h GEMM
__global__ void __launch_bounds__(256) k_count_h(const int* __restrict__ ei, int E,
                                                 const float* __restrict__ x,
                                                 const float* __restrict__ W) {
    int tid = threadIdx.x;
    if (blockIdx.x < 1024) {
        int e = blockIdx.x * 256 + tid;
        if (e < E) atomicAdd(&g_cnt[ei[E + e]], 1);
        return;
    }
    __shared__ float sW[FIN * FOUT];   // 32 KB
#pragma unroll
    for (int i = 0; i < 8; i++)
        ((float4*)sW)[tid + i * 256] = ((const float4*)W)[tid + i * 256];
    __syncthreads();

    const int hb = blockIdx.x - 1024;            // 0..255
    const int n = hb * 32 + (tid & 31);          // node (lanes consecutive -> coalesced x)
    const int g = tid >> 5;                      // out group 0..7 (warp-uniform -> LDS bcast)
    const float4* sW4 = (const float4*)sW;

    unsigned long long acc2[4];
#pragma unroll
    for (int i = 0; i < 4; i++) acc2[i] = 0ull;

#pragma unroll 8
    for (int k = 0; k < FIN; k++) {
        float xv = __ldg(&x[k * N_NODES + n]);   // 128B coalesced per warp
        unsigned long long a2;
        asm("mov.b64 %0, {%1, %1};" : "=l"(a2) : "f"(xv));
        float4 w0 = sW4[k * 16 + g * 2];         // broadcast LDS.128
        float4 w1 = sW4[k * 16 + g * 2 + 1];
        unsigned long long p0, p1, p2, p3;
        asm("mov.b64 %0, {%1, %2};" : "=l"(p0) : "f"(w0.x), "f"(w0.y));
        asm("mov.b64 %0, {%1, %2};" : "=l"(p1) : "f"(w0.z), "f"(w0.w));
        asm("mov.b64 %0, {%1, %2};" : "=l"(p2) : "f"(w1.x), "f"(w1.y));
        asm("mov.b64 %0, {%1, %2};" : "=l"(p3) : "f"(w1.z), "f"(w1.w));
        asm("fma.rn.f32x2 %0, %1, %2, %0;" : "+l"(acc2[0]) : "l"(a2), "l"(p0));
        asm("fma.rn.f32x2 %0, %1, %2, %0;" : "+l"(acc2[1]) : "l"(a2), "l"(p1));
        asm("fma.rn.f32x2 %0, %1, %2, %0;" : "+l"(acc2[2]) : "l"(a2), "l"(p2));
        asm("fma.rn.f32x2 %0, %1, %2, %0;" : "+l"(acc2[3]) : "l"(a2), "l"(p3));
    }
    float* hp = &g_h[n * FOUT + g * 8];
    float v0, v1, v2, v3, v4, v5, v6, v7;
    asm("mov.b64 {%0, %1}, %2;" : "=f"(v0), "=f"(v1) : "l"(acc2[0]));
    asm("mov.b64 {%0, %1}, %2;" : "=f"(v2), "=f"(v3) : "l"(acc2[1]));
    asm("mov.b64 {%0, %1}, %2;" : "=f"(v4), "=f"(v5) : "l"(acc2[2]));
    asm("mov.b64 {%0, %1}, %2;" : "=f"(v6), "=f"(v7) : "l"(acc2[3]));
    ((float4*)hp)[0] = make_float4(v0, v1, v2, v3);
    ((float4*)hp)[1] = make_float4(v4, v5, v6, v7);
}

// ---------------------------------------------------------------- launch 2: dinv + z = h*dinv^2 + b
__global__ void k_zinit(const float* __restrict__ b) {
    int gid = blockIdx.x * blockDim.x + threadIdx.x;   // N * 16
    int n = gid >> 4, q = gid & 15;
    float dinv = rsqrtf((float)(g_cnt[n] + 1));
    if (q == 0) g_dinv[n] = dinv;
    float c = dinv * dinv;
    float4 h = *(const float4*)&g_h[n * FOUT + q * 4];
    float4 bb = __ldg(&((const float4*)b)[q]);
    float4 z;
    z.x = fmaf(h.x, c, bb.x);
    z.y = fmaf(h.y, c, bb.y);
    z.z = fmaf(h.z, c, bb.z);
    z.w = fmaf(h.w, c, bb.w);
    *(float4*)&g_z[n * FOUT + q * 4] = z;
}

// ---------------------------------------------------------------- launch 3: edge scatter, vector red
__global__ void k_edges(const int* __restrict__ ei, int E) {
    int gid = blockIdx.x * blockDim.x + threadIdx.x;   // E * 16
    int e = gid >> 4, q = gid & 15;
    if (e >= E) return;
    int s = __ldg(&ei[e]);
    int d = __ldg(&ei[E + e]);
    float c = __ldg(&g_dinv[s]) * __ldg(&g_dinv[d]);
    float4 h = *(const float4*)&g_h[s * FOUT + q * 4];
    float* zp = &g_z[d * FOUT + q * 4];
    asm volatile("red.global.add.v4.f32 [%0], {%1, %2, %3, %4};"
                 :: "l"(zp), "f"(h.x * c), "f"(h.y * c), "f"(h.z * c), "f"(h.w * c)
                 : "memory");
}

// ---------------------------------------------------------------- launch 4: split-bf16 HMMA GEMM
__device__ __forceinline__ uint32_t smem_u32(const void* p) {
    uint32_t a;
    asm("{ .reg .u64 t; cvta.to.shared.u64 t, %1; cvt.u32.u64 %0, t; }" : "=r"(a) : "l"(p));
    return a;
}
__device__ __forceinline__ float sigmoid_tanh(float v) {
    float t;
    asm("tanh.approx.f32 %0, %1;" : "=f"(t) : "f"(0.5f * v));
    return fmaf(0.5f, t, 0.5f);
}
__device__ __forceinline__ void split2(float x, float y, uint32_t& hi, uint32_t& lo) {
    asm("cvt.rn.bf16x2.f32 %0, %1, %2;" : "=r"(hi) : "f"(y), "f"(x));   // hi16=y, lo16=x
    float hx = __uint_as_float(hi << 16);
    float hy = __uint_as_float(hi & 0xFFFF0000u);
    float rx = x - hx, ry = y - hy;
    asm("cvt.rn.bf16x2.f32 %0, %1, %2;" : "=r"(lo) : "f"(ry), "f"(rx));
}
#define LDSM4(r0, r1, r2, r3, addr) \
    asm volatile("ldmatrix.sync.aligned.m8n8.x4.shared.b16 {%0,%1,%2,%3}, [%4];" \
                 : "=r"(r0), "=r"(r1), "=r"(r2), "=r"(r3) : "r"(addr))
#define MMA16816(d, a, b0v, b1v) \
    asm volatile("mma.sync.aligned.m16n8k16.row.col.f32.bf16.bf16.f32 " \
                 "{%0,%1,%2,%3}, {%4,%5,%6,%7}, {%8,%9}, {%0,%1,%2,%3};" \
                 : "+f"((d)[0]), "+f"((d)[1]), "+f"((d)[2]), "+f"((d)[3]) \
                 : "r"((a)[0]), "r"((a)[1]), "r"((a)[2]), "r"((a)[3]), \
                   "r"(b0v), "r"(b1v))

// B staged-slot s6 (0..63, within 64-col warp tile) holds actual column:
//   a = (s6>>4)*16 + ((s6>>1)&3)*4 + ((s6>>3)&1)*2 + (s6&1)
// => fragment (j, c=lane&3, e) owns actual column (j>>1)*16 + c*4 + (j&1)*2 + e
__device__ __forceinline__ int bperm(int s6) {
    return ((s6 >> 4) << 4) + (((s6 >> 1) & 3) << 2) + (((s6 >> 3) & 1) << 1) + (s6 & 1);
}

#define GEMM_SMEM (4 * 128 * SA * 2)

__global__ void __launch_bounds__(256) k_gemm_mma(float* __restrict__ out) {
    const int bi = blockIdx.y, bj = blockIdx.x;
    if (bj < bi) {
        if (bj == 0 && bi >= 1 && bi <= 32)
            g_cnt[(bi - 1) * 256 + threadIdx.x] = 0;   // re-zero for next replay
        return;
    }
    const int i0 = bi * 128, j0 = bj * 128;
    extern __shared__ char dsm[];
    char* pAH = dsm;
    char* pAL = pAH + 128 * SA * 2;
    char* pBH = pAL + 128 * SA * 2;
    char* pBL = pBH + 128 * SA * 2;

    const int tid = threadIdx.x, lane = tid & 31, wid = tid >> 5;

    // ---- stage + bf16 split (B rows permuted per bperm) ----
#pragma unroll
    for (int it = 0; it < 8; it++) {
        int idx = tid + it * 256;          // 0..2047
        int row = idx >> 4, q = idx & 15;
        uint32_t o = (uint32_t)(row * (SA * 2) + q * 8);
        float4 v = *(const float4*)&g_z[(i0 + row) * FOUT + q * 4];
        uint32_t h0, l0, h1, l1;
        split2(v.x, v.y, h0, l0);
        split2(v.z, v.w, h1, l1);
        *(uint2*)(pAH + o) = make_uint2(h0, h1);
        *(uint2*)(pAL + o) = make_uint2(l0, l1);
        int bsrc = (row & 64) + bperm(row & 63);        // permuted source row for B
        float4 u = *(const float4*)&g_z[(j0 + bsrc) * FOUT + q * 4];
        split2(u.x, u.y, h0, l0);
        split2(u.z, u.w, h1, l1);
        *(uint2*)(pBH + o) = make_uint2(h0, h1);
        *(uint2*)(pBL + o) = make_uint2(l0, l1);
    }
    __syncthreads();

    const uint32_t aAH = smem_u32(pAH), aAL = smem_u32(pAL);
    const uint32_t aBH = smem_u32(pBH), aBL = smem_u32(pBL);

    const int wr = wid & 3, wc = wid >> 2;
    const int mbase = wr * 32, nbase = wc * 64;

    float d[2][8][4];
#pragma unroll
    for (int mi = 0; mi < 2; mi++)
#pragma unroll
        for (int j = 0; j < 8; j++)
#pragma unroll
            for (int t = 0; t < 4; t++) d[mi][j][t] = 0.f;

    const int arow = lane & 15, ahalf = lane >> 4;
    const int brow = (lane & 7) + 8 * ((lane >> 3) & 1);
    const int bhalf = lane >> 4;

#pragma unroll
    for (int ks = 0; ks < 4; ks++) {
        const int kb = ks * 16;
        uint32_t ah[2][4], al[2][4];
#pragma unroll
        for (int mi = 0; mi < 2; mi++) {
            uint32_t off = (uint32_t)(((mbase + mi * 16 + arow) * SA + kb + ahalf * 8) * 2);
            LDSM4(ah[mi][0], ah[mi][1], ah[mi][2], ah[mi][3], aAH + off);
            LDSM4(al[mi][0], al[mi][1], al[mi][2], al[mi][3], aAL + off);
        }
        uint32_t bh[8][2], bl[8][2];
#pragma unroll
        for (int jh = 0; jh < 4; jh++) {
            uint32_t off = (uint32_t)(((nbase + jh * 16 + brow) * SA + kb + bhalf * 8) * 2);
            uint32_t r0, r1, r2, r3;
            LDSM4(r0, r1, r2, r3, aBH + off);
            bh[jh * 2][0] = r0; bh[jh * 2][1] = r2;
            bh[jh * 2 + 1][0] = r1; bh[jh * 2 + 1][1] = r3;
            LDSM4(r0, r1, r2, r3, aBL + off);
            bl[jh * 2][0] = r0; bl[jh * 2][1] = r2;
            bl[jh * 2 + 1][0] = r1; bl[jh * 2 + 1][1] = r3;
        }
#pragma unroll
        for (int mi = 0; mi < 2; mi++)
#pragma unroll
            for (int j = 0; j < 8; j++) {
                MMA16816(d[mi][j], ah[mi], bh[j][0], bh[j][1]);
                MMA16816(d[mi][j], ah[mi], bl[j][0], bl[j][1]);
                MMA16816(d[mi][j], al[mi], bh[j][0], bh[j][1]);
            }
    }

    // ---- epilogue: sigmoid in place, vectorized direct stores, scalar mirror ----
#pragma unroll
    for (int mi = 0; mi < 2; mi++)
#pragma unroll
        for (int j = 0; j < 8; j++)
#pragma unroll
            for (int t = 0; t < 4; t++) d[mi][j][t] = sigmoid_tanh(d[mi][j][t]);

    const int fr = lane >> 2;            // 0..7
    const int lc = lane & 3;             // col group: owns cols q*16 + lc*4 .. +3
#pragma unroll
    for (int mi = 0; mi < 2; mi++) {
        const int gr0 = i0 + mbase + mi * 16 + fr;
#pragma unroll
        for (int q = 0; q < 3 + 1; q++) {
            const int gc = j0 + nbase + q * 16 + lc * 4;
            // row gr0: regs [0],[1] of fragment pair (2q, 2q+1)
            *(float4*)&out[(size_t)gr0 * N_NODES + gc] =
                make_float4(d[mi][2 * q][0], d[mi][2 * q][1],
                            d[mi][2 * q + 1][0], d[mi][2 * q + 1][1]);
            *(float4*)&out[(size_t)(gr0 + 8) * N_NODES + gc] =
                make_float4(d[mi][2 * q][2], d[mi][2 * q][3],
                            d[mi][2 * q + 1][2], d[mi][2 * q + 1][3]);
        }
        if (bi != bj) {
#pragma unroll
            for (int j = 0; j < 8; j++) {
                const int gc = j0 + nbase + (j >> 1) * 16 + lc * 4 + (j & 1) * 2;
                out[(size_t)gc * N_NODES + gr0]           = d[mi][j][0];
                out[(size_t)(gc + 1) * N_NODES + gr0]     = d[mi][j][1];
                out[(size_t)gc * N_NODES + gr0 + 8]       = d[mi][j][2];
                out[(size_t)(gc + 1) * N_NODES + gr0 + 8] = d[mi][j][3];
            }
        }
    }
}

// ----------------------------------------------------------------
extern "C" void kernel_launch(void* const* d_in, const int* in_sizes, int n_in,
                              void* d_out, int out_size) {
    const float* x  = (const float*)d_in[0];       // [128, 8192]
    const int*   ei = (const int*)d_in[1];         // [2, E] int32
    const float* W  = (const float*)d_in[2];       // [128, 64]
    const float* b  = (const float*)d_in[3];       // [64]
    float* out = (float*)d_out;                    // [8192, 8192]
    const int E = in_sizes[1] / 2;

    cudaFuncSetAttribute(k_gemm_mma, cudaFuncAttributeMaxDynamicSharedMemorySize, GEMM_SMEM);

    k_count_h<<<1024 + 256, 256>>>(ei, E, x, W);             // 1
    k_zinit<<<(N_NODES * 16) / 256, 256>>>(b);               // 2
    k_edges<<<(E * 16) / 256, 256>>>(ei, E);                 // 3
    dim3 grid(N_NODES / 128, N_NODES / 128);                 // symmetric grid
    k_gemm_mma<<<grid, 256, GEMM_SMEM>>>(out);               // 4 <- ncu captures this
}